// round 17
// baseline (speedup 1.0000x reference)
#include <cuda_runtime.h>
#include <cstdint>

// Problem constants (fixed by the dataset)
#define N_NODES 50000
#define E_EDGES 1600000
#define IN_DIM  256
#define HID     512
#define OUT_DIM 256
#define NBLK    ((N_NODES + 255) / 256)   // 196 scan blocks

// ---- GEMM tiling: 128x64 block, 8 warps, warp tile 32x32, K-chunk 32 fp32 ----
#define ASTRIDE 36   // smem row stride in floats (32 + 4 pad); 144B, 16B-aligned

// -------- scratch (module-static; no runtime allocation) --------
__device__ __align__(16) float g_dinv[N_NODES];
__device__ __align__(16) float g_t[N_NODES];
__device__ __align__(16) float g_ax[(size_t)N_NODES * IN_DIM];   // agg acc; reused as q after GEMM2
__device__ __align__(16) float g_h2[(size_t)N_NODES * HID];      // sigmoid(layer1), fp32
__device__ __align__(16) float g_w1h[(size_t)HID * IN_DIM];      // (W_ae@W1)^T tf32-hi [512][256]
__device__ __align__(16) float g_w1l[(size_t)HID * IN_DIM];      // tf32-lo residual
__device__ __align__(16) float g_w2h[(size_t)OUT_DIM * HID];     // W2^T tf32-hi [256][512]
__device__ __align__(16) float g_w2l[(size_t)OUT_DIM * HID];
__device__ __align__(16) float g_bb[HID];                        // b_ae @ W1
__device__ int g_is64;
// CSR scratch
__device__ __align__(16) int g_degi[N_NODES];    // in-degree (excl self loop)
__device__ __align__(16) int g_exc[N_NODES];     // in-block exclusive prefix
__device__ __align__(16) int g_bsum[NBLK];       // per-block sums
__device__ __align__(16) int g_boff[NBLK];       // per-block exclusive offsets
__device__ __align__(16) int g_rowptr[N_NODES];  // CSR row start
__device__ __align__(16) int g_fill[N_NODES];    // atomic fill cursor
__device__ __align__(16) int g_csr[E_EDGES];     // src ids grouped by dst

// -------- helpers --------
__device__ __forceinline__ float sigmoidf(float z) { return 1.0f / (1.0f + __expf(-z)); }

// fp32 -> tf32 hi/lo split: hi = rna(v); lo = rna(v - hi). hi bits are a valid fp32.
#define CVT2(H, L, V) do { \
    asm("cvt.rna.tf32.f32 %0, %1;" : "=r"(H) : "f"(V)); \
    float r_ = (V) - __uint_as_float(H); \
    asm("cvt.rna.tf32.f32 %0, %1;" : "=r"(L) : "f"(r_)); } while (0)

// m16n8k8 tf32 MMA on a named float4 accumulator (scalar operands only).
#define MMAT(C, A0, A1, A2, A3, B0, B1) \
    asm volatile("mma.sync.aligned.m16n8k8.row.col.f32.tf32.tf32.f32 " \
        "{%0,%1,%2,%3}, {%4,%5,%6,%7}, {%8,%9}, {%0,%1,%2,%3};" \
        : "+f"((C).x), "+f"((C).y), "+f"((C).z), "+f"((C).w) \
        : "r"(A0), "r"(A1), "r"(A2), "r"(A3), "r"(B0), "r"(B1))

// Split a float4 to tf32 hi/lo and store both smem tiles (float4 stores).
#define SPLITST(ROW, COLB, V) do { \
    uint32_t h0_, l0_, h1_, l1_, h2_, l2_, h3_, l3_; \
    CVT2(h0_, l0_, (V).x); CVT2(h1_, l1_, (V).y); \
    CVT2(h2_, l2_, (V).z); CVT2(h3_, l3_, (V).w); \
    *(float4*)&Ah[ROW][COLB] = make_float4(__uint_as_float(h0_), __uint_as_float(h1_), \
                                           __uint_as_float(h2_), __uint_as_float(h3_)); \
    *(float4*)&Al[ROW][COLB] = make_float4(__uint_as_float(l0_), __uint_as_float(l1_), \
                                           __uint_as_float(l2_), __uint_as_float(l3_)); } while (0)

// A fragments from pre-split smem (no cvt), 3-term MMA per n-subtile.
#define DO_MT(C0, C1, C2, C3, ROFF) do { \
    uint32_t ah0_ = __float_as_uint(Ah[rA0 + (ROFF)][kq]); \
    uint32_t ah1_ = __float_as_uint(Ah[rA0 + (ROFF) + 8][kq]); \
    uint32_t ah2_ = __float_as_uint(Ah[rA0 + (ROFF)][kq4]); \
    uint32_t ah3_ = __float_as_uint(Ah[rA0 + (ROFF) + 8][kq4]); \
    uint32_t al0_ = __float_as_uint(Al[rA0 + (ROFF)][kq]); \
    uint32_t al1_ = __float_as_uint(Al[rA0 + (ROFF) + 8][kq]); \
    uint32_t al2_ = __float_as_uint(Al[rA0 + (ROFF)][kq4]); \
    uint32_t al3_ = __float_as_uint(Al[rA0 + (ROFF) + 8][kq4]); \
    MMAT(C0, ah0_, ah1_, ah2_, ah3_, bh00, bh01); \
    MMAT(C0, ah0_, ah1_, ah2_, ah3_, bl00, bl01); \
    MMAT(C0, al0_, al1_, al2_, al3_, bh00, bh01); \
    MMAT(C1, ah0_, ah1_, ah2_, ah3_, bh10, bh11); \
    MMAT(C1, ah0_, ah1_, ah2_, ah3_, bl10, bl11); \
    MMAT(C1, al0_, al1_, al2_, al3_, bh10, bh11); \
    MMAT(C2, ah0_, ah1_, ah2_, ah3_, bh20, bh21); \
    MMAT(C2, ah0_, ah1_, ah2_, ah3_, bl20, bl21); \
    MMAT(C2, al0_, al1_, al2_, al3_, bh20, bh21); \
    MMAT(C3, ah0_, ah1_, ah2_, ah3_, bh30, bh31); \
    MMAT(C3, ah0_, ah1_, ah2_, ah3_, bl30, bl31); \
    MMAT(C3, al0_, al1_, al2_, al3_, bh30, bh31); } while (0)

// B fragments via LDG from pre-split weights (L1-resident), A from smem.
#define KSTEPG() do { \
    const int kq  = ks * 8 + lq; \
    const int kq4 = kq + 4; \
    const int ko_ = cko + ks * 8; \
    uint32_t bh00 = pBh[ko_],             bh01 = pBh[ko_ + 4]; \
    uint32_t bh10 = pBh[ko_ + 8 * KT],    bh11 = pBh[ko_ + 8 * KT + 4]; \
    uint32_t bh20 = pBh[ko_ + 16 * KT],   bh21 = pBh[ko_ + 16 * KT + 4]; \
    uint32_t bh30 = pBh[ko_ + 24 * KT],   bh31 = pBh[ko_ + 24 * KT + 4]; \
    uint32_t bl00 = pBl[ko_],             bl01 = pBl[ko_ + 4]; \
    uint32_t bl10 = pBl[ko_ + 8 * KT],    bl11 = pBl[ko_ + 8 * KT + 4]; \
    uint32_t bl20 = pBl[ko_ + 16 * KT],   bl21 = pBl[ko_ + 16 * KT + 4]; \
    uint32_t bl30 = pBl[ko_ + 24 * KT],   bl31 = pBl[ko_ + 24 * KT + 4]; \
    DO_MT(c00, c01, c02, c03, 0); \
    DO_MT(c10, c11, c12, c13, 16); } while (0)

// Read edge endpoint `which` (0=src, 1=dst) of edge e, dtype-agnostic.
__device__ __forceinline__ int edge_at(const void* ei, int which, int e) {
    if (g_is64) return (int)((const long long*)ei)[(size_t)which * E_EDGES + e];
    return ((const int*)ei)[(size_t)which * E_EDGES + e];
}

// -------- dtype detection --------
__global__ void k_detect(const int* __restrict__ ei32) {
    if (blockIdx.x == 0) {
        int is64 = 1;
        for (int i = 0; i < 1024; i++)
            if (ei32[2 * i + 1] != 0) { is64 = 0; break; }
        if (threadIdx.x == 0) g_is64 = is64;
    }
}

// -------- degree + dinv --------
__global__ void k_zero() {
    int i = blockIdx.x * blockDim.x + threadIdx.x;
    if (i < N_NODES) g_degi[i] = 0;
}
__global__ void k_count(const void* __restrict__ ei) {
    int e = blockIdx.x * blockDim.x + threadIdx.x;
    if (e < E_EDGES) atomicAdd(&g_degi[edge_at(ei, 1, e)], 1);
}
__global__ void k_dinv() {
    int i = blockIdx.x * blockDim.x + threadIdx.x;
    if (i < N_NODES) {
        float d = 1.0f + (float)g_degi[i];    // self loop + in-edges
        g_dinv[i] = rsqrtf(d);
    }
}

// -------- CSR build: block scan + aux scan + combine + fill --------
__global__ void k_scan1() {
    __shared__ int s[256];
    int i = blockIdx.x * 256 + threadIdx.x;
    int v = (i < N_NODES) ? g_degi[i] : 0;
    s[threadIdx.x] = v;
    __syncthreads();
    #pragma unroll
    for (int off = 1; off < 256; off <<= 1) {
        int t = (threadIdx.x >= off) ? s[threadIdx.x - off] : 0;
        __syncthreads();
        s[threadIdx.x] += t;
        __syncthreads();
    }
    if (i < N_NODES) g_exc[i] = s[threadIdx.x] - v;
    if (threadIdx.x == 255) g_bsum[blockIdx.x] = s[255];
}
__global__ void k_scan2() {
    __shared__ int s[256];
    int v = (threadIdx.x < NBLK) ? g_bsum[threadIdx.x] : 0;
    s[threadIdx.x] = v;
    __syncthreads();
    #pragma unroll
    for (int off = 1; off < 256; off <<= 1) {
        int t = (threadIdx.x >= off) ? s[threadIdx.x - off] : 0;
        __syncthreads();
        s[threadIdx.x] += t;
        __syncthreads();
    }
    if (threadIdx.x < NBLK) g_boff[threadIdx.x] = s[threadIdx.x] - v;
}
__global__ void k_scan3() {
    int i = blockIdx.x * 256 + threadIdx.x;
    if (i < N_NODES) {
        int r = g_exc[i] + g_boff[blockIdx.x];
        g_rowptr[i] = r;
        g_fill[i] = r;
    }
}
__global__ void k_fill(const void* __restrict__ ei) {
    int e = blockIdx.x * blockDim.x + threadIdx.x;
    if (e < E_EDGES) {
        int dst = edge_at(ei, 1, e);
        int pos = atomicAdd(&g_fill[dst], 1);
        g_csr[pos] = edge_at(ei, 0, e);
    }
}

// -------- gather 1: g_ax[v] = x[v]*dinv[v] + sum_src dinv[src]*x[src]; g_t[v] too --------
__global__ void k_gather1(const float* __restrict__ x) {
    int v = blockIdx.x * 8 + (threadIdx.x >> 5);
    if (v >= N_NODES) return;
    int lane = threadIdx.x & 31;
    int beg = g_rowptr[v];
    int end = beg + g_degi[v];
    float dv = g_dinv[v];
    const float4* xv = (const float4*)(x + (size_t)v * IN_DIM);
    float4 a0 = xv[lane];
    float4 a1 = xv[lane + 32];
    a0.x *= dv; a0.y *= dv; a0.z *= dv; a0.w *= dv;
    a1.x *= dv; a1.y *= dv; a1.z *= dv; a1.w *= dv;
    float t = dv;
    int e = beg;
    #pragma unroll 1
    for (; e + 2 <= end; e += 2) {
        int s0 = g_csr[e], s1 = g_csr[e + 1];
        float w0 = g_dinv[s0], w1 = g_dinv[s1];
        const float4* x0 = (const float4*)(x + (size_t)s0 * IN_DIM);
        const float4* x1 = (const float4*)(x + (size_t)s1 * IN_DIM);
        float4 p0 = x0[lane];
        float4 p1 = x0[lane + 32];
        float4 q0 = x1[lane];
        float4 q1 = x1[lane + 32];
        a0.x += w0 * p0.x + w1 * q0.x; a0.y += w0 * p0.y + w1 * q0.y;
        a0.z += w0 * p0.z + w1 * q0.z; a0.w += w0 * p0.w + w1 * q0.w;
        a1.x += w0 * p1.x + w1 * q1.x; a1.y += w0 * p1.y + w1 * q1.y;
        a1.z += w0 * p1.z + w1 * q1.z; a1.w += w0 * p1.w + w1 * q1.w;
        t += w0 + w1;
    }
    if (e < end) {
        int s0 = g_csr[e];
        float w0 = g_dinv[s0];
        const float4* x0 = (const float4*)(x + (size_t)s0 * IN_DIM);
        float4 p0 = x0[lane];
        float4 p1 = x0[lane + 32];
        a0.x += w0 * p0.x; a0.y += w0 * p0.y; a0.z += w0 * p0.z; a0.w += w0 * p0.w;
        a1.x += w0 * p1.x; a1.y += w0 * p1.y; a1.z += w0 * p1.z; a1.w += w0 * p1.w;
        t += w0;
    }
    float4* ax = (float4*)(g_ax + (size_t)v * IN_DIM);
    ax[lane] = a0;
    ax[lane + 32] = a1;
    if (lane == 0) g_t[v] = t;
}

// -------- gather 2 (+fused final): out[v] = sigmoid(dinv[v]*(q[v]+sum q[src]) + b2) --------
__global__ void k_gather2(const float* __restrict__ b2, float* __restrict__ out) {
    int v = blockIdx.x * 8 + (threadIdx.x >> 5);
    if (v >= N_NODES) return;
    int lane = threadIdx.x & 31;
    int beg = g_rowptr[v];
    int end = beg + g_degi[v];
    const float4* qv = (const float4*)(g_ax + (size_t)v * OUT_DIM);
    float4 a0 = qv[lane];
    float4 a1 = qv[lane + 32];
    int e = beg;
    #pragma unroll 1
    for (; e + 2 <= end; e += 2) {
        int s0 = g_csr[e], s1 = g_csr[e + 1];
        const float4* x0 = (const float4*)(g_ax + (size_t)s0 * OUT_DIM);
        const float4* x1 = (const float4*)(g_ax + (size_t)s1 * OUT_DIM);
        float4 p0 = x0[lane];
        float4 p1 = x0[lane + 32];
        float4 q0 = x1[lane];
        float4 q1 = x1[lane + 32];
        a0.x += p0.x + q0.x; a0.y += p0.y + q0.y;
        a0.z += p0.z + q0.z; a0.w += p0.w + q0.w;
        a1.x += p1.x + q1.x; a1.y += p1.y + q1.y;
        a1.z += p1.z + q1.z; a1.w += p1.w + q1.w;
    }
    if (e < end) {
        int s0 = g_csr[e];
        const float4* x0 = (const float4*)(g_ax + (size_t)s0 * OUT_DIM);
        float4 p0 = x0[lane];
        float4 p1 = x0[lane + 32];
        a0.x += p0.x; a0.y += p0.y; a0.z += p0.z; a0.w += p0.w;
        a1.x += p1.x; a1.y += p1.y; a1.z += p1.z; a1.w += p1.w;
    }
    float dv = g_dinv[v];
    float4 b0 = ((const float4*)b2)[lane];
    float4 b1 = ((const float4*)b2)[lane + 32];
    a0.x = sigmoidf(dv * a0.x + b0.x); a0.y = sigmoidf(dv * a0.y + b0.y);
    a0.z = sigmoidf(dv * a0.z + b0.z); a0.w = sigmoidf(dv * a0.w + b0.w);
    a1.x = sigmoidf(dv * a1.x + b1.x); a1.y = sigmoidf(dv * a1.y + b1.y);
    a1.z = sigmoidf(dv * a1.z + b1.z); a1.w = sigmoidf(dv * a1.w + b1.w);
    float4* op = (float4*)(out + (size_t)v * OUT_DIM);
    op[lane] = a0;
    op[lane + 32] = a1;
}

// -------- weight prep: compute + tf32 hi/lo pre-split --------
// w1{h,l}[j][k] = split((W_ae @ W1)[k][j])
__global__ void k_wc(const float* __restrict__ W_ae, const float* __restrict__ W1) {
    __shared__ float wa[HID];
    int k = blockIdx.y;                       // 0..255
    int j = blockIdx.x * 256 + threadIdx.x;   // 0..511
    for (int m = threadIdx.x; m < HID; m += 256) wa[m] = W_ae[k * HID + m];
    __syncthreads();
    float acc = 0.0f;
    #pragma unroll 8
    for (int m = 0; m < HID; m++) acc = fmaf(wa[m], W1[m * HID + j], acc);
    uint32_t h, l; CVT2(h, l, acc);
    g_w1h[(size_t)j * IN_DIM + k] = __uint_as_float(h);
    g_w1l[(size_t)j * IN_DIM + k] = __uint_as_float(l);
}
__global__ void k_bb(const float* __restrict__ b_ae, const float* __restrict__ W1) {
    int j = blockIdx.x * 256 + threadIdx.x;
    if (j < HID) {
        float acc = 0.0f;
        for (int m = 0; m < HID; m++) acc = fmaf(b_ae[m], W1[m * HID + j], acc);
        g_bb[j] = acc;
    }
}
// w2{h,l}[j][k] = split(W2[k][j])
__global__ void k_wt2(const float* __restrict__ W2) {
    int idx = blockIdx.x * 256 + threadIdx.x;   // < 512*256
    int kk = idx >> 8;      // 0..511
    int j  = idx & 255;     // 0..255
    uint32_t h, l; CVT2(h, l, W2[kk * OUT_DIM + j]);
    g_w2h[(size_t)j * HID + kk] = __uint_as_float(h);
    g_w2l[(size_t)j * HID + kk] = __uint_as_float(l);
}

// -------- epilogue helpers --------
__device__ __forceinline__ void ep1(float vx, float vy, int r, int col,
                                    const float* __restrict__ bias) {
    if (r < N_NODES) {
        float s1 = g_dinv[r] * g_t[r];
        float2 o = make_float2(sigmoidf(vx + s1 * g_bb[col] + bias[col]),
                               sigmoidf(vy + s1 * g_bb[col + 1] + bias[col + 1]));
        *(float2*)(g_h2 + (size_t)r * HID + col) = o;
    }
}
__device__ __forceinline__ void ep2(float vx, float vy, int r, int col,
                                    float* __restrict__ unused) {
    if (r < N_NODES) {
        float dv = g_dinv[r];
        *(float2*)(g_ax + (size_t)r * OUT_DIM + col) = make_float2(dv * vx, dv * vy);
    }
}

#define EPIW(EP, C, RO, CO, LAST) do { \
    EP((C).x, (C).y, rbase + (RO), cbase + (CO), LAST); \
    EP((C).z, (C).w, rbase + (RO) + 8, cbase + (CO), LAST); } while (0)

// -------- GEMM1: g_h2 = sigmoid(dinv.*(g_ax) @ Wc + s*bb + b1)  [K=256] --------
__global__ __launch_bounds__(256) void k_gemm1(const float* __restrict__ bias) {
    __shared__ float Ah[128][ASTRIDE];
    __shared__ float Al[128][ASTRIDE];
    const int tid = threadIdx.x;
    const int wid = tid >> 5, lane = tid & 31;
    const int lr = lane >> 2, lq = lane & 3;
    const int warp_m = wid & 3, warp_n = wid >> 2;
    const int row0 = blockIdx.x * 128;
    const int col0 = blockIdx.y * 64;
    const int rA0 = warp_m * 32 + lr;
    const int KT = IN_DIM;

    const uint32_t* pBh = (const uint32_t*)g_w1h + (size_t)(col0 + warp_n * 32 + lr) * IN_DIM + lq;
    const uint32_t* pBl = (const uint32_t*)g_w1l + (size_t)(col0 + warp_n * 32 + lr) * IN_DIM + lq;

    const int arow = tid >> 1, acol = (tid & 1) * 16;
    int gar = row0 + arow; if (gar > N_NODES - 1) gar = N_NODES - 1;
    const float da = g_dinv[gar];
    const float* pA = g_ax + (size_t)gar * IN_DIM + acol;

    float4 c00 = {0,0,0,0}, c01 = {0,0,0,0}, c02 = {0,0,0,0}, c03 = {0,0,0,0};
    float4 c10 = {0,0,0,0}, c11 = {0,0,0,0}, c12 = {0,0,0,0}, c13 = {0,0,0,0};

    float4 ra0 = *(const float4*)(pA + 0);
    float4 ra1 = *(const float4*)(pA + 4);
    float4 ra2 = *(const float4*)(pA + 8);
    float4 ra3 = *(const float4*)(pA + 12);

    #pragma unroll 1
    for (int c = 0; c < IN_DIM / 32; c++) {
        float4 s0 = make_float4(ra0.x * da, ra0.y * da, ra0.z * da, ra0.w * da);
        float4 s1 = make_float4(ra1.x * da, ra1.y * da, ra1.z * da, ra1.w * da);
        float4 s2 = make_float4(ra2.x * da, ra2.y * da, ra2.z * da, ra2.w * da);
        float4 s3 = make_float4(ra3.x * da, ra3.y * da, ra3.z * da, ra3.w * da);
        SPLITST(arow, acol + 0,  s0);
        SPLITST(arow, acol + 4,  s1);
        SPLITST(arow, acol + 8,  s2);
        SPLITST(arow, acol + 12, s3);
        __syncthreads();
        if (c + 1 < IN_DIM / 32) {
            const float* p_ = pA + (c + 1) * 32;
            ra0 = *(const float4*)(p_ + 0);
            ra1 = *(const float4*)(p_ + 4);
            ra2 = *(const float4*)(p_ + 8);
            ra3 = *(const float4*)(p_ + 12);
        }
        const int cko = c * 32;
        #pragma unroll 1
        for (int ks = 0; ks < 4; ks++) { const int cko2 = cko; (void)cko2; KSTEPG(); }
        __syncthreads();
    }

    const int rbase = row0 + warp_m * 32 + lr;
    const int cbase = col0 + warp_n * 32 + 2 * lq;
    EPIW(ep1, c00, 0, 0, bias);  EPIW(ep1, c01, 0, 8, bias);
    EPIW(ep1, c02, 0, 16, bias); EPIW(ep1, c03, 0, 24, bias);
    EPIW(ep1, c10, 16, 0, bias); EPIW(ep1, c11, 16, 8, bias);
    EPIW(ep1, c12, 16, 16, bias); EPIW(ep1, c13, 16, 24, bias);
}

// -------- GEMM2: q = dinv .* (g_h2 @ W2); q -> g_ax  [K=512] --------
__global__ __launch_bounds__(256) void k_gemm2() {
    __shared__ float Ah[128][ASTRIDE];
    __shared__ float Al[128][ASTRIDE];
    const int tid = threadIdx.x;
    const int wid = tid >> 5, lane = tid & 31;
    const int lr = lane >> 2, lq = lane & 3;
    const int warp_m = wid & 3, warp_n = wid >> 2;
    const int row0 = blockIdx.x * 128;
    const int col0 = blockIdx.y * 64;
    const int rA0 = warp_m * 32 + lr;
    const int KT = HID;

    const uint32_t* pBh = (const uint32_t*)g_w2h + (size_t)(col0 + warp_n * 32 + lr) * HID + lq;
    const uint32_t* pBl = (const uint32_t*)g_w2l + (size_t)(col0 + warp_n * 32 + lr) * HID + lq;

    const int arow = tid >> 1, acol = (tid & 1) * 16;
    int gar = row0 + arow; if (gar > N_NODES - 1) gar = N_NODES - 1;
    const float* pA = g_h2 + (size_t)gar * HID + acol;

    float4 c00 = {0,0,0,0}, c01 = {0,0,0,0}, c02 = {0,0,0,0}, c03 = {0,0,0,0};
    float4 c10 = {0,0,0,0}, c11 = {0,0,0,0}, c12 = {0,0,0,0}, c13 = {0,0,0,0};

    float4 ra0 = *(const float4*)(pA + 0);
    float4 ra1 = *(const float4*)(pA + 4);
    float4 ra2 = *(const float4*)(pA + 8);
    float4 ra3 = *(const float4*)(pA + 12);

    #pragma unroll 1
    for (int c = 0; c < HID / 32; c++) {
        SPLITST(arow, acol + 0,  ra0);
        SPLITST(arow, acol + 4,  ra1);
        SPLITST(arow, acol + 8,  ra2);
        SPLITST(arow, acol + 12, ra3);
        __syncthreads();
        if (c + 1 < HID / 32) {
            const float* p_ = pA + (c + 1) * 32;
            ra0 = *(const float4*)(p_ + 0);
            ra1 = *(const float4*)(p_ + 4);
            ra2 = *(const float4*)(p_ + 8);
            ra3 = *(const float4*)(p_ + 12);
        }
        const int cko = c * 32;
        #pragma unroll 1
        for (int ks = 0; ks < 4; ks++) { KSTEPG(); }
        __syncthreads();
    }

    const int rbase = row0 + warp_m * 32 + lr;
    const int cbase = col0 + warp_n * 32 + 2 * lq;
    EPIW(ep2, c00, 0, 0, nullptr);  EPIW(ep2, c01, 0, 8, nullptr);
    EPIW(ep2, c02, 0, 16, nullptr); EPIW(ep2, c03, 0, 24, nullptr);
    EPIW(ep2, c10, 16, 0, nullptr); EPIW(ep2, c11, 16, 8, nullptr);
    EPIW(ep2, c12, 16, 16, nullptr); EPIW(ep2, c13, 16, 24, nullptr);
}

// -------- launch --------
extern "C" void kernel_launch(void* const* d_in, const int* in_sizes, int n_in,
                              void* d_out, int out_size) {
    const float* x    = (const float*)d_in[0];
    const void*  ei   = d_in[1];
    const float* W_ae = (const float*)d_in[2];
    const float* b_ae = (const float*)d_in[3];
    const float* W1   = (const float*)d_in[4];
    const float* b1   = (const float*)d_in[5];
    const float* W2   = (const float*)d_in[6];
    const float* b2   = (const float*)d_in[7];
    float* out = (float*)d_out;

    k_detect<<<1, 32>>>((const int*)ei);
    k_zero<<<NBLK, 256>>>();
    k_count<<<(E_EDGES + 255) / 256, 256>>>(ei);
    k_dinv<<<NBLK, 256>>>();
    k_scan1<<<NBLK, 256>>>();
    k_scan2<<<1, 256>>>();
    k_scan3<<<NBLK, 256>>>();
    k_fill<<<(E_EDGES + 255) / 256, 256>>>(ei);
    k_gather1<<<(N_NODES + 7) / 8, 256>>>(x);
    k_wc<<<dim3(2, 256), 256>>>(W_ae, W1);
    k_bb<<<2, 256>>>(b_ae, W1);
    k_wt2<<<(HID * OUT_DIM) / 256, 256>>>(W2);

    k_gemm1<<<dim3((N_NODES + 127) / 128, HID / 64), 256>>>(b1);
    k_gemm2<<<dim3((N_NODES + 127) / 128, OUT_DIM / 64), 256>>>();

    k_gather2<<<(N_NODES + 7) / 8, 256>>>(b2, out);
}